// round 3
// baseline (speedup 1.0000x reference)
#include <cuda_runtime.h>
#include <cuda_bf16.h>

#define B_ 4
#define H_ 16
#define NQ 256
#define D_ 16

// Scratch for projected Q/K/V in [b][h][n][d] layout (no runtime allocation allowed).
__device__ float g_Q[B_ * H_ * NQ * D_];
__device__ float g_K[B_ * H_ * NQ * D_];
__device__ float g_V[B_ * H_ * NQ * D_];

// ---------------------------------------------------------------------------
// Kernel A: QKV projections.  out[m, hd] = sum_e A[m, e] * W[hd, e]
// (A and W are both row-major with K (=e) contiguous, so loads are coalesced.)
// Tiled 64x64, 256 threads, 4x4 micro-tile per thread, K-step 16.
// Writes directly into [b][h][n][d] scratch layout.
// ---------------------------------------------------------------------------
__global__ __launch_bounds__(256) void qkv_kernel(
    const float* __restrict__ row_emb, const float* __restrict__ col_emb,
    const float* __restrict__ Wq, const float* __restrict__ Wk,
    const float* __restrict__ Wv)
{
    __shared__ float As[16][68];   // [k][m], padded
    __shared__ float Ws[16][68];   // [k][n], padded

    const float* A; const float* W; float* O;
    int z = blockIdx.z;
    if (z == 0)      { A = row_emb; W = Wq; O = g_Q; }
    else if (z == 1) { A = col_emb; W = Wk; O = g_K; }
    else             { A = col_emb; W = Wv; O = g_V; }

    int m0 = blockIdx.y * 64;      // row tile (m = b*256 + n)
    int n0 = blockIdx.x * 64;      // col tile (hd)
    int t  = threadIdx.x;
    int tx = t & 15, ty = t >> 4;
    int lm = t >> 2, lk = (t & 3) * 4;   // load mapping: 64 rows x 16 k

    float acc[4][4];
    #pragma unroll
    for (int i = 0; i < 4; i++)
        #pragma unroll
        for (int j = 0; j < 4; j++) acc[i][j] = 0.f;

    for (int k0 = 0; k0 < 256; k0 += 16) {
        float4 av = *(const float4*)&A[(m0 + lm) * 256 + k0 + lk];
        float4 wv = *(const float4*)&W[(n0 + lm) * 256 + k0 + lk];
        __syncthreads();
        As[lk + 0][lm] = av.x; As[lk + 1][lm] = av.y;
        As[lk + 2][lm] = av.z; As[lk + 3][lm] = av.w;
        Ws[lk + 0][lm] = wv.x; Ws[lk + 1][lm] = wv.y;
        Ws[lk + 2][lm] = wv.z; Ws[lk + 3][lm] = wv.w;
        __syncthreads();
        #pragma unroll
        for (int k = 0; k < 16; k++) {
            float4 a  = *(const float4*)&As[k][ty * 4];
            float4 bq = *(const float4*)&Ws[k][tx * 4];
            float am[4] = {a.x, a.y, a.z, a.w};
            float bm[4] = {bq.x, bq.y, bq.z, bq.w};
            #pragma unroll
            for (int i = 0; i < 4; i++)
                #pragma unroll
                for (int j = 0; j < 4; j++)
                    acc[i][j] = fmaf(am[i], bm[j], acc[i][j]);
        }
    }

    // Scatter into [b][h][n][d] layout.  h,d constant per thread; b constant
    // per tile (64 | 256).
    int bb = (m0) >> 8;
    int hh = (n0 >> 4) + (tx >> 2);
    int dd = (tx & 3) * 4;
    #pragma unroll
    for (int i = 0; i < 4; i++) {
        int m = m0 + ty * 4 + i;
        int r = m & 255;
        float4 o = make_float4(acc[i][0], acc[i][1], acc[i][2], acc[i][3]);
        *(float4*)&O[((bb * H_ + hh) * NQ + r) * D_ + dd] = o;
    }
}

// ---------------------------------------------------------------------------
// Kernel B: fused scores + mixing-MLP + softmax + AV.
// One block per (b, h, 8-row tile); one warp per row; each lane owns 8 columns.
// K/V tiles live in shared (row stride 20 -> conflict-free LDS.128).
// mix2_bias is dropped: it is a per-row constant and softmax-invariant.
// ---------------------------------------------------------------------------
__global__ __launch_bounds__(256) void attn_kernel(
    const float* __restrict__ cost_mat,
    const float* __restrict__ mix1_w,   // [16][2][32]
    const float* __restrict__ mix1_b,   // [16][32]
    const float* __restrict__ mix2_w,   // [16][32][1]
    float* __restrict__ out)            // [B][R][H*D]
{
    __shared__ float  Ks[256][20];
    __shared__ float  Vs[256][20];
    __shared__ float4 mlp[32];          // (w1_dot, w1_cost, bias1, w2)

    int b = blockIdx.z, h = blockIdx.y, rt = blockIdx.x;
    int bh = b * H_ + h;
    int t = threadIdx.x;
    int lane = t & 31, w = t >> 5;

    // Cooperative load of K,V tiles (one row per thread, 64B contiguous each).
    {
        const float* Kg = g_K + bh * NQ * D_;
        const float* Vg = g_V + bh * NQ * D_;
        int c = t;
        #pragma unroll
        for (int j = 0; j < 4; j++) {
            *(float4*)&Ks[c][j * 4] = *(const float4*)&Kg[c * D_ + j * 4];
            *(float4*)&Vs[c][j * 4] = *(const float4*)&Vg[c * D_ + j * 4];
        }
    }
    if (t < 32) {
        mlp[t] = make_float4(mix1_w[h * 64 + t],        // weight on dot_score
                             mix1_w[h * 64 + 32 + t],   // weight on cost_score
                             mix1_b[h * 32 + t],
                             mix2_w[h * 32 + t]);
    }
    __syncthreads();

    int r = rt * 8 + w;

    // Broadcast-load this row's q into registers.
    float q[16];
    {
        const float* Qg = g_Q + (bh * NQ + r) * D_;
        #pragma unroll
        for (int j = 0; j < 4; j++) {
            float4 qv = *(const float4*)&Qg[j * 4];
            q[j * 4 + 0] = qv.x; q[j * 4 + 1] = qv.y;
            q[j * 4 + 2] = qv.z; q[j * 4 + 3] = qv.w;
        }
    }
    const float* costRow = cost_mat + (b * NQ + r) * NQ;

    // Phase 1: dot scores (scaled) + cost loads, 8 columns per lane.
    float dotv[8], costv[8];
    #pragma unroll
    for (int i = 0; i < 8; i++) {
        int c = i * 32 + lane;
        float s = 0.f;
        #pragma unroll
        for (int j = 0; j < 4; j++) {
            float4 kv = *(const float4*)&Ks[c][j * 4];
            s = fmaf(q[j * 4 + 0], kv.x, s);
            s = fmaf(q[j * 4 + 1], kv.y, s);
            s = fmaf(q[j * 4 + 2], kv.z, s);
            s = fmaf(q[j * 4 + 3], kv.w, s);
        }
        dotv[i]  = s * 0.25f;            // 1/sqrt(16)
        costv[i] = __ldg(&costRow[c]);
    }

    // Phase 2: mixing MLP, m-outer so each weight vector loads once.
    float sc[8];
    #pragma unroll
    for (int i = 0; i < 8; i++) sc[i] = 0.f;
    #pragma unroll 4
    for (int m = 0; m < 32; m++) {
        float4 wv = mlp[m];
        #pragma unroll
        for (int i = 0; i < 8; i++) {
            float tm = fmaf(wv.y, costv[i], wv.z);
            tm = fmaf(wv.x, dotv[i], tm);
            tm = fmaxf(tm, 0.f);
            sc[i] = fmaf(wv.w, tm, sc[i]);
        }
    }

    // Phase 3: softmax over 256 columns (8 per lane + warp reduce).
    float mx = sc[0];
    #pragma unroll
    for (int i = 1; i < 8; i++) mx = fmaxf(mx, sc[i]);
    #pragma unroll
    for (int o = 16; o; o >>= 1) mx = fmaxf(mx, __shfl_xor_sync(0xffffffffu, mx, o));
    float sum = 0.f;
    #pragma unroll
    for (int i = 0; i < 8; i++) { sc[i] = __expf(sc[i] - mx); sum += sc[i]; }
    #pragma unroll
    for (int o = 16; o; o >>= 1) sum += __shfl_xor_sync(0xffffffffu, sum, o);
    float inv = 1.f / sum;

    // Phase 4: AV accumulation (unnormalized; divide at the end).
    float acc[16];
    #pragma unroll
    for (int d = 0; d < 16; d++) acc[d] = 0.f;
    #pragma unroll
    for (int i = 0; i < 8; i++) {
        int c = i * 32 + lane;
        float wg = sc[i];
        #pragma unroll
        for (int j = 0; j < 4; j++) {
            float4 vv = *(const float4*)&Vs[c][j * 4];
            acc[j * 4 + 0] = fmaf(wg, vv.x, acc[j * 4 + 0]);
            acc[j * 4 + 1] = fmaf(wg, vv.y, acc[j * 4 + 1]);
            acc[j * 4 + 2] = fmaf(wg, vv.z, acc[j * 4 + 2]);
            acc[j * 4 + 3] = fmaf(wg, vv.w, acc[j * 4 + 3]);
        }
    }

    // Cross-lane reduce: 16 butterfly chains; lane d keeps value d (static idx).
    float res = 0.f;
    #pragma unroll
    for (int d = 0; d < 16; d++) {
        float s = acc[d];
        #pragma unroll
        for (int o = 16; o; o >>= 1) s += __shfl_xor_sync(0xffffffffu, s, o);
        if (lane == d) res = s;
    }
    if (lane < 16)
        out[(b * NQ + r) * (H_ * D_) + h * D_ + lane] = res * inv;
}

extern "C" void kernel_launch(void* const* d_in, const int* in_sizes, int n_in,
                              void* d_out, int out_size)
{
    const float* row_emb  = (const float*)d_in[0];
    const float* col_emb  = (const float*)d_in[1];
    const float* cost_mat = (const float*)d_in[2];
    const float* Wq       = (const float*)d_in[3];
    const float* Wk       = (const float*)d_in[4];
    const float* Wv       = (const float*)d_in[5];
    const float* m1w      = (const float*)d_in[6];
    const float* m1b      = (const float*)d_in[7];
    const float* m2w      = (const float*)d_in[8];
    // d_in[9] = mix2_bias: softmax-invariant, intentionally unused.
    float* out = (float*)d_out;

    dim3 gA(4, 16, 3);   // n-tiles x m-tiles x {Q,K,V}
    qkv_kernel<<<gA, 256>>>(row_emb, col_emb, Wq, Wk, Wv);

    dim3 gB(32, 16, 4);  // row-tiles x heads x batch
    attn_kernel<<<gB, 256>>>(cost_mat, m1w, m1b, m2w, out);
}

// round 4
// speedup vs baseline: 1.0931x; 1.0931x over previous
#include <cuda_runtime.h>
#include <cuda_bf16.h>

#define B_ 4
#define H_ 16
#define NQ 256
#define D_ 16

typedef unsigned long long u64;

// ---- packed f32x2 helpers (sm_100a) ---------------------------------------
__device__ __forceinline__ u64 pk(float a, float b) {
    u64 r; asm("mov.b64 %0, {%1,%2};" : "=l"(r) : "f"(a), "f"(b)); return r;
}
__device__ __forceinline__ void upk(u64 v, float& a, float& b) {
    asm("mov.b64 {%0,%1}, %2;" : "=f"(a), "=f"(b) : "l"(v));
}
__device__ __forceinline__ u64 fma2_(u64 a, u64 b, u64 c) {
    u64 r; asm("fma.rn.f32x2 %0, %1, %2, %3;" : "=l"(r) : "l"(a), "l"(b), "l"(c));
    return r;
}

// Scratch for projected Q/K/V in [b][h][n][d] layout.
__device__ float g_Q[B_ * H_ * NQ * D_];
__device__ float g_K[B_ * H_ * NQ * D_];
__device__ float g_V[B_ * H_ * NQ * D_];

// ---------------------------------------------------------------------------
// Kernel A: QKV projections.  out[m, hd] = sum_e A[m, e] * W[hd, e]
// Tiled 64x64, 256 threads, 4x4 micro-tile, K-step 16, packed-f32x2 inner loop.
// ---------------------------------------------------------------------------
__global__ __launch_bounds__(256) void qkv_kernel(
    const float* __restrict__ row_emb, const float* __restrict__ col_emb,
    const float* __restrict__ Wq, const float* __restrict__ Wk,
    const float* __restrict__ Wv)
{
    __shared__ float As[16][68];   // [k][m], padded
    __shared__ float Ws[16][68];   // [k][n], padded

    const float* A; const float* W; float* O;
    int z = blockIdx.z;
    if (z == 0)      { A = row_emb; W = Wq; O = g_Q; }
    else if (z == 1) { A = col_emb; W = Wk; O = g_K; }
    else             { A = col_emb; W = Wv; O = g_V; }

    int m0 = blockIdx.y * 64;
    int n0 = blockIdx.x * 64;
    int t  = threadIdx.x;
    int tx = t & 15, ty = t >> 4;
    int lm = t >> 2, lk = (t & 3) * 4;

    u64 accp[4][2];                // [i][j-pair] -> (acc[i][2j], acc[i][2j+1])
    #pragma unroll
    for (int i = 0; i < 4; i++) { accp[i][0] = 0ull; accp[i][1] = 0ull; }

    for (int k0 = 0; k0 < 256; k0 += 16) {
        float4 av = *(const float4*)&A[(m0 + lm) * 256 + k0 + lk];
        float4 wv = *(const float4*)&W[(n0 + lm) * 256 + k0 + lk];
        __syncthreads();
        As[lk + 0][lm] = av.x; As[lk + 1][lm] = av.y;
        As[lk + 2][lm] = av.z; As[lk + 3][lm] = av.w;
        Ws[lk + 0][lm] = wv.x; Ws[lk + 1][lm] = wv.y;
        Ws[lk + 2][lm] = wv.z; Ws[lk + 3][lm] = wv.w;
        __syncthreads();
        #pragma unroll
        for (int k = 0; k < 16; k++) {
            float4 a  = *(const float4*)&As[k][ty * 4];
            float4 bq = *(const float4*)&Ws[k][tx * 4];
            u64 b01 = pk(bq.x, bq.y);      // adjacent regs from LDS.128 -> free
            u64 b23 = pk(bq.z, bq.w);
            float am[4] = {a.x, a.y, a.z, a.w};
            #pragma unroll
            for (int i = 0; i < 4; i++) {
                u64 aa = pk(am[i], am[i]);
                accp[i][0] = fma2_(aa, b01, accp[i][0]);
                accp[i][1] = fma2_(aa, b23, accp[i][1]);
            }
        }
    }

    int bb = m0 >> 8;
    int hh = (n0 >> 4) + (tx >> 2);
    int dd = (tx & 3) * 4;
    #pragma unroll
    for (int i = 0; i < 4; i++) {
        int m = m0 + ty * 4 + i;
        int r = m & 255;
        float4 o;
        upk(accp[i][0], o.x, o.y);
        upk(accp[i][1], o.z, o.w);
        *(float4*)&O[((bb * H_ + hh) * NQ + r) * D_ + dd] = o;
    }
}

// ---------------------------------------------------------------------------
// Kernel B: fused scores + mixing-MLP + softmax + AV.
// One block per (b, h, 16-row tile); one warp per TWO rows (halves per-row LDS
// traffic vs one-row-per-warp).  MLP + AV use packed f32x2 FMA.
// mix2_bias dropped (softmax-invariant per-row constant).
// ---------------------------------------------------------------------------
__global__ __launch_bounds__(256) void attn_kernel(
    const float* __restrict__ cost_mat,
    const float* __restrict__ mix1_w,   // [16][2][32]
    const float* __restrict__ mix1_b,   // [16][32]
    const float* __restrict__ mix2_w,   // [16][32][1]
    float* __restrict__ out)            // [B][R][H*D]
{
    __shared__ float Ks[256][20];
    __shared__ float Vs[256][20];
    __shared__ u64   mlpp[32][4];       // pre-packed broadcast pairs (wx,wy,bz,w2)

    int b = blockIdx.z, h = blockIdx.y, rt = blockIdx.x;
    int bh = b * H_ + h;
    int t = threadIdx.x;
    int lane = t & 31, w = t >> 5;

    // Cooperative K/V tile load (one 16-float row per thread).
    {
        const float* Kg = g_K + bh * NQ * D_;
        const float* Vg = g_V + bh * NQ * D_;
        #pragma unroll
        for (int j = 0; j < 4; j++) {
            *(float4*)&Ks[t][j * 4] = *(const float4*)&Kg[t * D_ + j * 4];
            *(float4*)&Vs[t][j * 4] = *(const float4*)&Vg[t * D_ + j * 4];
        }
    }
    if (t < 32) {
        float wx = mix1_w[h * 64 + t];        // weight on dot_score
        float wy = mix1_w[h * 64 + 32 + t];   // weight on cost_score
        float bz = mix1_b[h * 32 + t];
        float w2 = mix2_w[h * 32 + t];
        mlpp[t][0] = pk(wx, wx);
        mlpp[t][1] = pk(wy, wy);
        mlpp[t][2] = pk(bz, bz);
        mlpp[t][3] = pk(w2, w2);
    }
    __syncthreads();

    int r0 = rt * 16 + w * 2;     // this warp handles rows r0, r0+1

    // Both rows' q vectors in registers.
    float q0[16], q1[16];
    {
        const float* Qg = g_Q + (bh * NQ + r0) * D_;
        #pragma unroll
        for (int j = 0; j < 4; j++) {
            float4 a = *(const float4*)&Qg[j * 4];
            float4 c = *(const float4*)&Qg[16 + j * 4];
            q0[j * 4 + 0] = a.x; q0[j * 4 + 1] = a.y;
            q0[j * 4 + 2] = a.z; q0[j * 4 + 3] = a.w;
            q1[j * 4 + 0] = c.x; q1[j * 4 + 1] = c.y;
            q1[j * 4 + 2] = c.z; q1[j * 4 + 3] = c.w;
        }
    }
    const float* cr0 = cost_mat + (b * NQ + r0) * NQ;
    const float* cr1 = cr0 + NQ;

    // Phase 1: dot scores + cost loads, packed as column pairs.
    // Lane owns cols {i*32+lane : i in 0..7}; pair (2p, 2p+1).
    u64 dp0[4], dp1[4], cp0[4], cp1[4];
    #pragma unroll
    for (int p = 0; p < 4; p++) {
        int ca = (2 * p) * 32 + lane;
        int cb = ca + 32;
        float sa0 = 0.f, sa1 = 0.f, sb0 = 0.f, sb1 = 0.f;
        #pragma unroll
        for (int j = 0; j < 4; j++) {
            float4 ka = *(const float4*)&Ks[ca][j * 4];
            float4 kb = *(const float4*)&Ks[cb][j * 4];
            sa0 = fmaf(q0[j*4+0], ka.x, sa0); sa0 = fmaf(q0[j*4+1], ka.y, sa0);
            sa0 = fmaf(q0[j*4+2], ka.z, sa0); sa0 = fmaf(q0[j*4+3], ka.w, sa0);
            sa1 = fmaf(q1[j*4+0], ka.x, sa1); sa1 = fmaf(q1[j*4+1], ka.y, sa1);
            sa1 = fmaf(q1[j*4+2], ka.z, sa1); sa1 = fmaf(q1[j*4+3], ka.w, sa1);
            sb0 = fmaf(q0[j*4+0], kb.x, sb0); sb0 = fmaf(q0[j*4+1], kb.y, sb0);
            sb0 = fmaf(q0[j*4+2], kb.z, sb0); sb0 = fmaf(q0[j*4+3], kb.w, sb0);
            sb1 = fmaf(q1[j*4+0], kb.x, sb1); sb1 = fmaf(q1[j*4+1], kb.y, sb1);
            sb1 = fmaf(q1[j*4+2], kb.z, sb1); sb1 = fmaf(q1[j*4+3], kb.w, sb1);
        }
        dp0[p] = pk(sa0 * 0.25f, sb0 * 0.25f);     // 1/sqrt(16)
        dp1[p] = pk(sa1 * 0.25f, sb1 * 0.25f);
        cp0[p] = pk(__ldg(cr0 + ca), __ldg(cr0 + cb));
        cp1[p] = pk(__ldg(cr1 + ca), __ldg(cr1 + cb));
    }

    // Phase 2: mixing MLP, packed f32x2 (2 cols per op), 2 rows per warp.
    u64 s0[4], s1[4];
    #pragma unroll
    for (int p = 0; p < 4; p++) { s0[p] = 0ull; s1[p] = 0ull; }
    #pragma unroll 4
    for (int m = 0; m < 32; m++) {
        u64 wxx = mlpp[m][0], wyy = mlpp[m][1], wzz = mlpp[m][2], www = mlpp[m][3];
        #pragma unroll
        for (int p = 0; p < 4; p++) {
            u64 t0 = fma2_(wyy, cp0[p], wzz);
            t0 = fma2_(wxx, dp0[p], t0);
            float a0, b0; upk(t0, a0, b0);
            a0 = fmaxf(a0, 0.f); b0 = fmaxf(b0, 0.f);
            s0[p] = fma2_(www, pk(a0, b0), s0[p]);

            u64 t1 = fma2_(wyy, cp1[p], wzz);
            t1 = fma2_(wxx, dp1[p], t1);
            float a1, b1; upk(t1, a1, b1);
            a1 = fmaxf(a1, 0.f); b1 = fmaxf(b1, 0.f);
            s1[p] = fma2_(www, pk(a1, b1), s1[p]);
        }
    }

    // Phase 3: softmax per row (8 cols/lane + warp reduce).
    float sc0[8], sc1[8];
    #pragma unroll
    for (int p = 0; p < 4; p++) {
        upk(s0[p], sc0[2 * p], sc0[2 * p + 1]);
        upk(s1[p], sc1[2 * p], sc1[2 * p + 1]);
    }
    float mx0 = sc0[0], mx1 = sc1[0];
    #pragma unroll
    for (int i = 1; i < 8; i++) { mx0 = fmaxf(mx0, sc0[i]); mx1 = fmaxf(mx1, sc1[i]); }
    #pragma unroll
    for (int o = 16; o; o >>= 1) {
        mx0 = fmaxf(mx0, __shfl_xor_sync(0xffffffffu, mx0, o));
        mx1 = fmaxf(mx1, __shfl_xor_sync(0xffffffffu, mx1, o));
    }
    float sum0 = 0.f, sum1 = 0.f;
    #pragma unroll
    for (int i = 0; i < 8; i++) {
        sc0[i] = __expf(sc0[i] - mx0); sum0 += sc0[i];
        sc1[i] = __expf(sc1[i] - mx1); sum1 += sc1[i];
    }
    #pragma unroll
    for (int o = 16; o; o >>= 1) {
        sum0 += __shfl_xor_sync(0xffffffffu, sum0, o);
        sum1 += __shfl_xor_sync(0xffffffffu, sum1, o);
    }
    float inv0 = 1.f / sum0, inv1 = 1.f / sum1;

    // Phase 4: AV accumulation, packed over d pairs, V loaded once per 2 rows.
    u64 acc0[8], acc1[8];
    #pragma unroll
    for (int j = 0; j < 8; j++) { acc0[j] = 0ull; acc1[j] = 0ull; }
    #pragma unroll
    for (int i = 0; i < 8; i++) {
        int c = i * 32 + lane;
        u64 w0 = pk(sc0[i], sc0[i]);
        u64 w1 = pk(sc1[i], sc1[i]);
        #pragma unroll
        for (int j = 0; j < 4; j++) {
            float4 vv = *(const float4*)&Vs[c][j * 4];
            u64 vA = pk(vv.x, vv.y);
            u64 vB = pk(vv.z, vv.w);
            acc0[2 * j]     = fma2_(w0, vA, acc0[2 * j]);
            acc0[2 * j + 1] = fma2_(w0, vB, acc0[2 * j + 1]);
            acc1[2 * j]     = fma2_(w1, vA, acc1[2 * j]);
            acc1[2 * j + 1] = fma2_(w1, vB, acc1[2 * j + 1]);
        }
    }

    // Cross-lane reduce: 16 butterfly chains per row; lane d keeps value d.
    float a0f[16], a1f[16];
    #pragma unroll
    for (int j = 0; j < 8; j++) {
        upk(acc0[j], a0f[2 * j], a0f[2 * j + 1]);
        upk(acc1[j], a1f[2 * j], a1f[2 * j + 1]);
    }
    float res0 = 0.f, res1 = 0.f;
    #pragma unroll
    for (int d = 0; d < 16; d++) {
        float s = a0f[d];
        #pragma unroll
        for (int o = 16; o; o >>= 1) s += __shfl_xor_sync(0xffffffffu, s, o);
        if (lane == d) res0 = s;
        float s2 = a1f[d];
        #pragma unroll
        for (int o = 16; o; o >>= 1) s2 += __shfl_xor_sync(0xffffffffu, s2, o);
        if (lane == d) res1 = s2;
    }
    if (lane < 16) {
        out[(b * NQ + r0) * (H_ * D_) + h * D_ + lane]       = res0 * inv0;
        out[(b * NQ + r0 + 1) * (H_ * D_) + h * D_ + lane]   = res1 * inv1;
    }
}

extern "C" void kernel_launch(void* const* d_in, const int* in_sizes, int n_in,
                              void* d_out, int out_size)
{
    const float* row_emb  = (const float*)d_in[0];
    const float* col_emb  = (const float*)d_in[1];
    const float* cost_mat = (const float*)d_in[2];
    const float* Wq       = (const float*)d_in[3];
    const float* Wk       = (const float*)d_in[4];
    const float* Wv       = (const float*)d_in[5];
    const float* m1w      = (const float*)d_in[6];
    const float* m1b      = (const float*)d_in[7];
    const float* m2w      = (const float*)d_in[8];
    // d_in[9] = mix2_bias: softmax-invariant, intentionally unused.
    float* out = (float*)d_out;

    dim3 gA(4, 16, 3);   // n-tiles x m-tiles x {Q,K,V}
    qkv_kernel<<<gA, 256>>>(row_emb, col_emb, Wq, Wk, Wv);

    dim3 gB(16, 16, 4);  // 16-row tiles x heads x batch
    attn_kernel<<<gB, 256>>>(cost_mat, m1w, m1b, m2w, out);
}

// round 5
// speedup vs baseline: 1.1257x; 1.0298x over previous
#include <cuda_runtime.h>
#include <cuda_bf16.h>

#define B_ 4
#define H_ 16
#define NQ 256
#define D_ 16

typedef unsigned long long u64;

#define ABSM 0x7FFFFFFF7FFFFFFFULL

// ---- packed f32x2 helpers (sm_100a) ---------------------------------------
__device__ __forceinline__ u64 pk(float a, float b) {
    u64 r; asm("mov.b64 %0, {%1,%2};" : "=l"(r) : "f"(a), "f"(b)); return r;
}
__device__ __forceinline__ void upk(u64 v, float& a, float& b) {
    asm("mov.b64 {%0,%1}, %2;" : "=f"(a), "=f"(b) : "l"(v));
}
__device__ __forceinline__ u64 fma2_(u64 a, u64 b, u64 c) {
    u64 r; asm("fma.rn.f32x2 %0, %1, %2, %3;" : "=l"(r) : "l"(a), "l"(b), "l"(c));
    return r;
}
__device__ __forceinline__ u64 add2_(u64 a, u64 b) {
    u64 r; asm("add.rn.f32x2 %0, %1, %2;" : "=l"(r) : "l"(a), "l"(b));
    return r;
}

// Scratch for projected Q/K/V in [b][h][n][d] layout.
__device__ float g_Q[B_ * H_ * NQ * D_];
__device__ float g_K[B_ * H_ * NQ * D_];
__device__ float g_V[B_ * H_ * NQ * D_];

// ---------------------------------------------------------------------------
// Kernel A: QKV projections.  out[m, hd] = sum_e A[m, e] * W[hd, e]
// Tiled 64x64, 256 threads, 4x4 micro-tile, K-step 16, packed-f32x2 inner,
// software-pipelined global loads (prefetch next k-tile during compute).
// ---------------------------------------------------------------------------
__global__ __launch_bounds__(256) void qkv_kernel(
    const float* __restrict__ row_emb, const float* __restrict__ col_emb,
    const float* __restrict__ Wq, const float* __restrict__ Wk,
    const float* __restrict__ Wv)
{
    __shared__ float As[16][68];   // [k][m], padded
    __shared__ float Ws[16][68];   // [k][n], padded

    const float* A; const float* W; float* O;
    int z = blockIdx.z;
    if (z == 0)      { A = row_emb; W = Wq; O = g_Q; }
    else if (z == 1) { A = col_emb; W = Wk; O = g_K; }
    else             { A = col_emb; W = Wv; O = g_V; }

    int m0 = blockIdx.y * 64;
    int n0 = blockIdx.x * 64;
    int t  = threadIdx.x;
    int tx = t & 15, ty = t >> 4;
    int lm = t >> 2, lk = (t & 3) * 4;

    const float* Ap = &A[(m0 + lm) * 256 + lk];
    const float* Wp = &W[(n0 + lm) * 256 + lk];

    u64 accp[4][2];
    #pragma unroll
    for (int i = 0; i < 4; i++) { accp[i][0] = 0ull; accp[i][1] = 0ull; }

    // Prologue prefetch.
    float4 av = *(const float4*)Ap;
    float4 wv = *(const float4*)Wp;

    for (int k0 = 0; k0 < 256; k0 += 16) {
        __syncthreads();                  // previous iter done reading smem
        As[lk + 0][lm] = av.x; As[lk + 1][lm] = av.y;
        As[lk + 2][lm] = av.z; As[lk + 3][lm] = av.w;
        Ws[lk + 0][lm] = wv.x; Ws[lk + 1][lm] = wv.y;
        Ws[lk + 2][lm] = wv.z; Ws[lk + 3][lm] = wv.w;
        __syncthreads();
        if (k0 + 16 < 256) {              // prefetch overlaps compute below
            av = *(const float4*)(Ap + k0 + 16);
            wv = *(const float4*)(Wp + k0 + 16);
        }
        #pragma unroll
        for (int k = 0; k < 16; k++) {
            float4 a  = *(const float4*)&As[k][ty * 4];
            float4 bq = *(const float4*)&Ws[k][tx * 4];
            u64 b01 = pk(bq.x, bq.y);
            u64 b23 = pk(bq.z, bq.w);
            float am[4] = {a.x, a.y, a.z, a.w};
            #pragma unroll
            for (int i = 0; i < 4; i++) {
                u64 aa = pk(am[i], am[i]);
                accp[i][0] = fma2_(aa, b01, accp[i][0]);
                accp[i][1] = fma2_(aa, b23, accp[i][1]);
            }
        }
    }

    int bb = m0 >> 8;
    int hh = (n0 >> 4) + (tx >> 2);
    int dd = (tx & 3) * 4;
    #pragma unroll
    for (int i = 0; i < 4; i++) {
        int m = m0 + ty * 4 + i;
        int r = m & 255;
        float4 o;
        upk(accp[i][0], o.x, o.y);
        upk(accp[i][1], o.z, o.w);
        *(float4*)&O[((bb * H_ + hh) * NQ + r) * D_ + dd] = o;
    }
}

// ---------------------------------------------------------------------------
// Reduce-scatter over 32 lanes: input acc[8] packed u64 = 16 floats (d pairs).
// Returns full 32-lane sum for d = f(lane); every xor-1 lane pair agrees.
// ---------------------------------------------------------------------------
__device__ __forceinline__ float reduce16(const u64 acc[8], int lane, int& dOut)
{
    bool k16 = (lane & 16) == 0;
    u64 h[4];
    #pragma unroll
    for (int j = 0; j < 4; j++) {
        u64 send = k16 ? acc[4 + j] : acc[j];
        u64 recv = __shfl_xor_sync(0xffffffffu, send, 16);
        u64 mine = k16 ? acc[j] : acc[4 + j];
        h[j] = add2_(mine, recv);
    }
    bool k8 = (lane & 8) == 0;
    u64 g[2];
    #pragma unroll
    for (int j = 0; j < 2; j++) {
        u64 send = k8 ? h[2 + j] : h[j];
        u64 recv = __shfl_xor_sync(0xffffffffu, send, 8);
        u64 mine = k8 ? h[j] : h[2 + j];
        g[j] = add2_(mine, recv);
    }
    bool k4 = (lane & 4) == 0;
    {
        u64 send = k4 ? g[1] : g[0];
        u64 recv = __shfl_xor_sync(0xffffffffu, send, 4);
        u64 mine = k4 ? g[0] : g[1];
        g[0] = add2_(mine, recv);
    }
    float lo, hi; upk(g[0], lo, hi);
    bool k2 = (lane & 2) == 0;
    float send = k2 ? hi : lo;
    float recv = __shfl_xor_sync(0xffffffffu, send, 2);
    float s = (k2 ? lo : hi) + recv;
    s += __shfl_xor_sync(0xffffffffu, s, 1);
    dOut = ((lane & 16) >> 1) | ((lane & 8) >> 1) | ((lane & 4) >> 1) | ((lane & 2) >> 1);
    return s;
}

// ---------------------------------------------------------------------------
// Kernel B: fused scores + mixing-MLP + softmax + AV.
// One warp per TWO rows.  MLP uses packed f32x2 with the exact abs-relu
// identity  w2*relu(t) = (0.5*w2)*(t + |t|)  (no unpack, no fmax).
// 1/sqrt(16) folded into w1_dot.  mix2_bias dropped (softmax-invariant).
// ---------------------------------------------------------------------------
__global__ __launch_bounds__(256) void attn_kernel(
    const float* __restrict__ cost_mat,
    const float* __restrict__ mix1_w,   // [16][2][32]
    const float* __restrict__ mix1_b,   // [16][32]
    const float* __restrict__ mix2_w,   // [16][32][1]
    float* __restrict__ out)            // [B][R][H*D]
{
    __shared__ float Ks[256][20];
    __shared__ float Vs[256][20];
    __shared__ u64   mlpp[32][4];       // (wx*0.25 pair, wy pair, b1 pair, 0.5*w2 pair)

    int b = blockIdx.z, h = blockIdx.y, rt = blockIdx.x;
    int bh = b * H_ + h;
    int t = threadIdx.x;
    int lane = t & 31, w = t >> 5;
    int r0 = rt * 16 + w * 2;           // this warp handles rows r0, r0+1

    // ---- early global loads (hide latency under the smem staging) ----
    const float* cr0 = cost_mat + (b * NQ + r0) * NQ;
    const float* cr1 = cr0 + NQ;
    u64 cp0[4], cp1[4];
    #pragma unroll
    for (int p = 0; p < 4; p++) {
        int ca = (2 * p) * 32 + lane;
        cp0[p] = pk(__ldg(cr0 + ca), __ldg(cr0 + ca + 32));
        cp1[p] = pk(__ldg(cr1 + ca), __ldg(cr1 + ca + 32));
    }
    float q0[16], q1[16];
    {
        const float* Qg = g_Q + (bh * NQ + r0) * D_;
        #pragma unroll
        for (int j = 0; j < 4; j++) {
            float4 a = *(const float4*)&Qg[j * 4];
            float4 c = *(const float4*)&Qg[16 + j * 4];
            q0[j*4+0] = a.x; q0[j*4+1] = a.y; q0[j*4+2] = a.z; q0[j*4+3] = a.w;
            q1[j*4+0] = c.x; q1[j*4+1] = c.y; q1[j*4+2] = c.z; q1[j*4+3] = c.w;
        }
    }

    // ---- cooperative K/V tile staging ----
    {
        const float* Kg = g_K + bh * NQ * D_;
        const float* Vg = g_V + bh * NQ * D_;
        #pragma unroll
        for (int j = 0; j < 4; j++) {
            *(float4*)&Ks[t][j * 4] = *(const float4*)&Kg[t * D_ + j * 4];
            *(float4*)&Vs[t][j * 4] = *(const float4*)&Vg[t * D_ + j * 4];
        }
    }
    if (t < 32) {
        float wx = mix1_w[h * 64 + t] * 0.25f;   // fold 1/sqrt(D)
        float wy = mix1_w[h * 64 + 32 + t];
        float bz = mix1_b[h * 32 + t];
        float hw = mix2_w[h * 32 + t] * 0.5f;    // fold 0.5 of abs-relu identity
        mlpp[t][0] = pk(wx, wx);
        mlpp[t][1] = pk(wy, wy);
        mlpp[t][2] = pk(bz, bz);
        mlpp[t][3] = pk(hw, hw);
    }
    __syncthreads();

    // ---- Phase 1: raw dot scores (scale folded into wx) ----
    u64 dp0[4], dp1[4];
    #pragma unroll
    for (int p = 0; p < 4; p++) {
        int ca = (2 * p) * 32 + lane;
        int cb = ca + 32;
        float sa0 = 0.f, sa1 = 0.f, sb0 = 0.f, sb1 = 0.f;
        #pragma unroll
        for (int j = 0; j < 4; j++) {
            float4 ka = *(const float4*)&Ks[ca][j * 4];
            float4 kb = *(const float4*)&Ks[cb][j * 4];
            sa0 = fmaf(q0[j*4+0], ka.x, sa0); sa0 = fmaf(q0[j*4+1], ka.y, sa0);
            sa0 = fmaf(q0[j*4+2], ka.z, sa0); sa0 = fmaf(q0[j*4+3], ka.w, sa0);
            sa1 = fmaf(q1[j*4+0], ka.x, sa1); sa1 = fmaf(q1[j*4+1], ka.y, sa1);
            sa1 = fmaf(q1[j*4+2], ka.z, sa1); sa1 = fmaf(q1[j*4+3], ka.w, sa1);
            sb0 = fmaf(q0[j*4+0], kb.x, sb0); sb0 = fmaf(q0[j*4+1], kb.y, sb0);
            sb0 = fmaf(q0[j*4+2], kb.z, sb0); sb0 = fmaf(q0[j*4+3], kb.w, sb0);
            sb1 = fmaf(q1[j*4+0], kb.x, sb1); sb1 = fmaf(q1[j*4+1], kb.y, sb1);
            sb1 = fmaf(q1[j*4+2], kb.z, sb1); sb1 = fmaf(q1[j*4+3], kb.w, sb1);
        }
        dp0[p] = pk(sa0, sb0);
        dp1[p] = pk(sa1, sb1);
    }

    // ---- Phase 2: mixing MLP, packed f32x2 with abs-relu ----
    u64 s0[4], s1[4];
    #pragma unroll
    for (int p = 0; p < 4; p++) { s0[p] = 0ull; s1[p] = 0ull; }
    #pragma unroll 4
    for (int m = 0; m < 32; m++) {
        u64 wxx = mlpp[m][0], wyy = mlpp[m][1], wzz = mlpp[m][2], hww = mlpp[m][3];
        #pragma unroll
        for (int p = 0; p < 4; p++) {
            u64 t0 = fma2_(wyy, cp0[p], wzz);
            t0 = fma2_(wxx, dp0[p], t0);
            u64 r0v = add2_(t0, t0 & ABSM);          // 2t if >0 else 0 (exact)
            s0[p] = fma2_(hww, r0v, s0[p]);

            u64 t1 = fma2_(wyy, cp1[p], wzz);
            t1 = fma2_(wxx, dp1[p], t1);
            u64 r1v = add2_(t1, t1 & ABSM);
            s1[p] = fma2_(hww, r1v, s1[p]);
        }
    }

    // ---- Phase 3: softmax per row ----
    float sc0[8], sc1[8];
    #pragma unroll
    for (int p = 0; p < 4; p++) {
        upk(s0[p], sc0[2 * p], sc0[2 * p + 1]);
        upk(s1[p], sc1[2 * p], sc1[2 * p + 1]);
    }
    float mx0 = sc0[0], mx1 = sc1[0];
    #pragma unroll
    for (int i = 1; i < 8; i++) { mx0 = fmaxf(mx0, sc0[i]); mx1 = fmaxf(mx1, sc1[i]); }
    #pragma unroll
    for (int o = 16; o; o >>= 1) {
        mx0 = fmaxf(mx0, __shfl_xor_sync(0xffffffffu, mx0, o));
        mx1 = fmaxf(mx1, __shfl_xor_sync(0xffffffffu, mx1, o));
    }
    float sum0 = 0.f, sum1 = 0.f;
    #pragma unroll
    for (int i = 0; i < 8; i++) {
        sc0[i] = __expf(sc0[i] - mx0); sum0 += sc0[i];
        sc1[i] = __expf(sc1[i] - mx1); sum1 += sc1[i];
    }
    #pragma unroll
    for (int o = 16; o; o >>= 1) {
        sum0 += __shfl_xor_sync(0xffffffffu, sum0, o);
        sum1 += __shfl_xor_sync(0xffffffffu, sum1, o);
    }
    float inv0 = 1.f / sum0, inv1 = 1.f / sum1;

    // ---- Phase 4: AV accumulation (packed over d pairs) ----
    u64 acc0[8], acc1[8];
    #pragma unroll
    for (int j = 0; j < 8; j++) { acc0[j] = 0ull; acc1[j] = 0ull; }
    #pragma unroll
    for (int i = 0; i < 8; i++) {
        int c = i * 32 + lane;
        u64 w0 = pk(sc0[i], sc0[i]);
        u64 w1 = pk(sc1[i], sc1[i]);
        #pragma unroll
        for (int j = 0; j < 4; j++) {
            float4 vv = *(const float4*)&Vs[c][j * 4];
            u64 vA = pk(vv.x, vv.y);
            u64 vB = pk(vv.z, vv.w);
            acc0[2 * j]     = fma2_(w0, vA, acc0[2 * j]);
            acc0[2 * j + 1] = fma2_(w0, vB, acc0[2 * j + 1]);
            acc1[2 * j]     = fma2_(w1, vA, acc1[2 * j]);
            acc1[2 * j + 1] = fma2_(w1, vB, acc1[2 * j + 1]);
        }
    }

    // ---- Phase 5: reduce-scatter epilogue ----
    int d0;
    float res0 = reduce16(acc0, lane, d0);
    int d1;
    float res1 = reduce16(acc1, lane, d1);
    if ((lane & 1) == 0) {
        out[(b * NQ + r0)     * (H_ * D_) + h * D_ + d0] = res0 * inv0;
        out[(b * NQ + r0 + 1) * (H_ * D_) + h * D_ + d1] = res1 * inv1;
    }
}

extern "C" void kernel_launch(void* const* d_in, const int* in_sizes, int n_in,
                              void* d_out, int out_size)
{
    const float* row_emb  = (const float*)d_in[0];
    const float* col_emb  = (const float*)d_in[1];
    const float* cost_mat = (const float*)d_in[2];
    const float* Wq       = (const float*)d_in[3];
    const float* Wk       = (const float*)d_in[4];
    const float* Wv       = (const float*)d_in[5];
    const float* m1w      = (const float*)d_in[6];
    const float* m1b      = (const float*)d_in[7];
    const float* m2w      = (const float*)d_in[8];
    // d_in[9] = mix2_bias: softmax-invariant, intentionally unused.
    float* out = (float*)d_out;

    dim3 gA(4, 16, 3);   // n-tiles x m-tiles x {Q,K,V}
    qkv_kernel<<<gA, 256>>>(row_emb, col_emb, Wq, Wk, Wv);

    dim3 gB(16, 16, 4);  // 16-row tiles x heads x batch
    attn_kernel<<<gB, 256>>>(cost_mat, m1w, m1b, m2w, out);
}

// round 6
// speedup vs baseline: 1.1713x; 1.0405x over previous
#include <cuda_runtime.h>
#include <cuda_bf16.h>

#define B_ 4
#define H_ 16
#define NQ 256
#define D_ 16

typedef unsigned long long u64;

#define ABSM 0x7FFFFFFF7FFFFFFFULL

// ---- packed f32x2 helpers (sm_100a) ---------------------------------------
__device__ __forceinline__ u64 pk(float a, float b) {
    u64 r; asm("mov.b64 %0, {%1,%2};" : "=l"(r) : "f"(a), "f"(b)); return r;
}
__device__ __forceinline__ void upk(u64 v, float& a, float& b) {
    asm("mov.b64 {%0,%1}, %2;" : "=f"(a), "=f"(b) : "l"(v));
}
__device__ __forceinline__ u64 fma2_(u64 a, u64 b, u64 c) {
    u64 r; asm("fma.rn.f32x2 %0, %1, %2, %3;" : "=l"(r) : "l"(a), "l"(b), "l"(c));
    return r;
}
__device__ __forceinline__ u64 add2_(u64 a, u64 b) {
    u64 r; asm("add.rn.f32x2 %0, %1, %2;" : "=l"(r) : "l"(a), "l"(b));
    return r;
}
__device__ __forceinline__ u64 mul2_(u64 a, u64 b) {
    u64 r; asm("mul.rn.f32x2 %0, %1, %2;" : "=l"(r) : "l"(a), "l"(b));
    return r;
}

// Scratch for projected Q/K/V in [b][h][n][d] layout.
__device__ float g_Q[B_ * H_ * NQ * D_];
__device__ float g_K[B_ * H_ * NQ * D_];
__device__ float g_V[B_ * H_ * NQ * D_];

// ---------------------------------------------------------------------------
// Kernel A: QKV projections.  out[m, hd] = sum_e A[m, e] * W[hd, e]
// Tiled 64x64, 256 threads, 4x4 micro-tile, K-step 16, packed-f32x2 inner,
// double-buffered smem (1 sync per k-step, store overlaps compute).
// ---------------------------------------------------------------------------
__global__ __launch_bounds__(256) void qkv_kernel(
    const float* __restrict__ row_emb, const float* __restrict__ col_emb,
    const float* __restrict__ Wq, const float* __restrict__ Wk,
    const float* __restrict__ Wv)
{
    __shared__ float As[2][16][68];   // [stage][k][m], padded
    __shared__ float Ws[2][16][68];   // [stage][k][n], padded

    const float* A; const float* W; float* O;
    int z = blockIdx.z;
    if (z == 0)      { A = row_emb; W = Wq; O = g_Q; }
    else if (z == 1) { A = col_emb; W = Wk; O = g_K; }
    else             { A = col_emb; W = Wv; O = g_V; }

    int m0 = blockIdx.y * 64;
    int n0 = blockIdx.x * 64;
    int t  = threadIdx.x;
    int tx = t & 15, ty = t >> 4;
    int lm = t >> 2, lk = (t & 3) * 4;

    const float* Ap = &A[(m0 + lm) * 256 + lk];
    const float* Wp = &W[(n0 + lm) * 256 + lk];

    u64 accp[4][2];
    #pragma unroll
    for (int i = 0; i < 4; i++) { accp[i][0] = 0ull; accp[i][1] = 0ull; }

    // Prologue: fill stage 0.
    {
        float4 av = *(const float4*)Ap;
        float4 wv = *(const float4*)Wp;
        As[0][lk + 0][lm] = av.x; As[0][lk + 1][lm] = av.y;
        As[0][lk + 2][lm] = av.z; As[0][lk + 3][lm] = av.w;
        Ws[0][lk + 0][lm] = wv.x; Ws[0][lk + 1][lm] = wv.y;
        Ws[0][lk + 2][lm] = wv.z; Ws[0][lk + 3][lm] = wv.w;
    }
    __syncthreads();

    for (int k0 = 0; k0 < 256; k0 += 16) {
        int cur = (k0 >> 4) & 1, nxt = cur ^ 1;
        float4 av, wv;
        bool more = (k0 + 16) < 256;
        if (more) {
            av = *(const float4*)(Ap + k0 + 16);
            wv = *(const float4*)(Wp + k0 + 16);
        }
        #pragma unroll
        for (int k = 0; k < 16; k++) {
            float4 a  = *(const float4*)&As[cur][k][ty * 4];
            float4 bq = *(const float4*)&Ws[cur][k][tx * 4];
            u64 b01 = pk(bq.x, bq.y);
            u64 b23 = pk(bq.z, bq.w);
            float am[4] = {a.x, a.y, a.z, a.w};
            #pragma unroll
            for (int i = 0; i < 4; i++) {
                u64 aa = pk(am[i], am[i]);
                accp[i][0] = fma2_(aa, b01, accp[i][0]);
                accp[i][1] = fma2_(aa, b23, accp[i][1]);
            }
        }
        if (more) {
            As[nxt][lk + 0][lm] = av.x; As[nxt][lk + 1][lm] = av.y;
            As[nxt][lk + 2][lm] = av.z; As[nxt][lk + 3][lm] = av.w;
            Ws[nxt][lk + 0][lm] = wv.x; Ws[nxt][lk + 1][lm] = wv.y;
            Ws[nxt][lk + 2][lm] = wv.z; Ws[nxt][lk + 3][lm] = wv.w;
            __syncthreads();
        }
    }

    int bb = m0 >> 8;
    int hh = (n0 >> 4) + (tx >> 2);
    int dd = (tx & 3) * 4;
    #pragma unroll
    for (int i = 0; i < 4; i++) {
        int m = m0 + ty * 4 + i;
        int r = m & 255;
        float4 o;
        upk(accp[i][0], o.x, o.y);
        upk(accp[i][1], o.z, o.w);
        *(float4*)&O[((bb * H_ + hh) * NQ + r) * D_ + dd] = o;
    }
}

// ---------------------------------------------------------------------------
// Reduce-scatter over 32 lanes: input acc[8] packed u64 = 16 floats (d pairs).
// Returns full 32-lane sum for d = f(lane); every xor-1 lane pair agrees.
// ---------------------------------------------------------------------------
__device__ __forceinline__ float reduce16(const u64 acc[8], int lane, int& dOut)
{
    bool k16 = (lane & 16) == 0;
    u64 h[4];
    #pragma unroll
    for (int j = 0; j < 4; j++) {
        u64 send = k16 ? acc[4 + j] : acc[j];
        u64 recv = __shfl_xor_sync(0xffffffffu, send, 16);
        u64 mine = k16 ? acc[j] : acc[4 + j];
        h[j] = add2_(mine, recv);
    }
    bool k8 = (lane & 8) == 0;
    u64 g[2];
    #pragma unroll
    for (int j = 0; j < 2; j++) {
        u64 send = k8 ? h[2 + j] : h[j];
        u64 recv = __shfl_xor_sync(0xffffffffu, send, 8);
        u64 mine = k8 ? h[j] : h[2 + j];
        g[j] = add2_(mine, recv);
    }
    bool k4 = (lane & 4) == 0;
    {
        u64 send = k4 ? g[1] : g[0];
        u64 recv = __shfl_xor_sync(0xffffffffu, send, 4);
        u64 mine = k4 ? g[0] : g[1];
        g[0] = add2_(mine, recv);
    }
    float lo, hi; upk(g[0], lo, hi);
    bool k2 = (lane & 2) == 0;
    float send = k2 ? hi : lo;
    float recv = __shfl_xor_sync(0xffffffffu, send, 2);
    float s = (k2 ? lo : hi) + recv;
    s += __shfl_xor_sync(0xffffffffu, s, 1);
    dOut = ((lane & 16) >> 1) | ((lane & 8) >> 1) | ((lane & 4) >> 1) | ((lane & 2) >> 1);
    return s;
}

// ---------------------------------------------------------------------------
// Kernel B: fused scores + mixing-MLP + softmax + AV.
// One warp per TWO rows.  MLP identity:
//   sum_m w2*relu(t_m) = A*dot + B*cost + C + sum_m (0.5*w2_m)*|t_m|
// with A = sum 0.5*w2*w1a, B = sum 0.5*w2*w1b; C softmax-invariant (dropped,
// as is mix2_bias).  1/sqrt(D) folded into w1a.  launch_bounds(256,3) caps
// regs at 85 -> 3 blocks/SM.
// ---------------------------------------------------------------------------
__global__ __launch_bounds__(256, 3) void attn_kernel(
    const float* __restrict__ cost_mat,
    const float* __restrict__ mix1_w,   // [16][2][32]
    const float* __restrict__ mix1_b,   // [16][32]
    const float* __restrict__ mix2_w,   // [16][32][1]
    float* __restrict__ out)            // [B][R][H*D]
{
    __shared__ float Ks[256][20];
    __shared__ float Vs[256][20];
    __shared__ u64   mlpp[32][4];       // (wx pair, wy pair, b1 pair, 0.5*w2 pair)
    __shared__ u64   ABs[2];            // packed (A,A), (B,B)

    int b = blockIdx.z, h = blockIdx.y, rt = blockIdx.x;
    int bh = b * H_ + h;
    int t = threadIdx.x;
    int lane = t & 31, w = t >> 5;
    int r0 = rt * 16 + w * 2;           // this warp handles rows r0, r0+1

    // ---- cooperative K/V tile staging ----
    {
        const float* Kg = g_K + bh * NQ * D_;
        const float* Vg = g_V + bh * NQ * D_;
        #pragma unroll
        for (int j = 0; j < 4; j++) {
            *(float4*)&Ks[t][j * 4] = *(const float4*)&Kg[t * D_ + j * 4];
            *(float4*)&Vs[t][j * 4] = *(const float4*)&Vg[t * D_ + j * 4];
        }
    }
    if (t < 32) {
        float wxv = mix1_w[h * 64 + t] * 0.25f;   // fold 1/sqrt(D)
        float wyv = mix1_w[h * 64 + 32 + t];
        float bzv = mix1_b[h * 32 + t];
        float hwv = mix2_w[h * 32 + t] * 0.5f;    // fold 0.5 of abs-relu identity
        mlpp[t][0] = pk(wxv, wxv);
        mlpp[t][1] = pk(wyv, wyv);
        mlpp[t][2] = pk(bzv, bzv);
        mlpp[t][3] = pk(hwv, hwv);
        float a  = hwv * wxv;
        float bb = hwv * wyv;
        #pragma unroll
        for (int o = 16; o; o >>= 1) {
            a  += __shfl_xor_sync(0xffffffffu, a, o);
            bb += __shfl_xor_sync(0xffffffffu, bb, o);
        }
        if (t == 0) { ABs[0] = pk(a, a); ABs[1] = pk(bb, bb); }
    }
    __syncthreads();

    // ---- Phase 1: raw dot scores (scale folded into wx) ----
    float q0[16], q1[16];
    {
        const float* Qg = g_Q + (bh * NQ + r0) * D_;
        #pragma unroll
        for (int j = 0; j < 4; j++) {
            float4 a = *(const float4*)&Qg[j * 4];
            float4 c = *(const float4*)&Qg[16 + j * 4];
            q0[j*4+0] = a.x; q0[j*4+1] = a.y; q0[j*4+2] = a.z; q0[j*4+3] = a.w;
            q1[j*4+0] = c.x; q1[j*4+1] = c.y; q1[j*4+2] = c.z; q1[j*4+3] = c.w;
        }
    }
    u64 dp0[4], dp1[4];
    #pragma unroll
    for (int p = 0; p < 4; p++) {
        int ca = (2 * p) * 32 + lane;
        int cb = ca + 32;
        float sa0 = 0.f, sa1 = 0.f, sb0 = 0.f, sb1 = 0.f;
        #pragma unroll
        for (int j = 0; j < 4; j++) {
            float4 ka = *(const float4*)&Ks[ca][j * 4];
            float4 kb = *(const float4*)&Ks[cb][j * 4];
            sa0 = fmaf(q0[j*4+0], ka.x, sa0); sa0 = fmaf(q0[j*4+1], ka.y, sa0);
            sa0 = fmaf(q0[j*4+2], ka.z, sa0); sa0 = fmaf(q0[j*4+3], ka.w, sa0);
            sa1 = fmaf(q1[j*4+0], ka.x, sa1); sa1 = fmaf(q1[j*4+1], ka.y, sa1);
            sa1 = fmaf(q1[j*4+2], ka.z, sa1); sa1 = fmaf(q1[j*4+3], ka.w, sa1);
            sb0 = fmaf(q0[j*4+0], kb.x, sb0); sb0 = fmaf(q0[j*4+1], kb.y, sb0);
            sb0 = fmaf(q0[j*4+2], kb.z, sb0); sb0 = fmaf(q0[j*4+3], kb.w, sb0);
            sb1 = fmaf(q1[j*4+0], kb.x, sb1); sb1 = fmaf(q1[j*4+1], kb.y, sb1);
            sb1 = fmaf(q1[j*4+2], kb.z, sb1); sb1 = fmaf(q1[j*4+3], kb.w, sb1);
        }
        dp0[p] = pk(sa0, sb0);
        dp1[p] = pk(sa1, sb1);
    }

    // ---- cost loads (after phase 1 so q regs can retire first) ----
    const float* cr0 = cost_mat + (b * NQ + r0) * NQ;
    const float* cr1 = cr0 + NQ;
    u64 cp0[4], cp1[4];
    #pragma unroll
    for (int p = 0; p < 4; p++) {
        int ca = (2 * p) * 32 + lane;
        cp0[p] = pk(__ldg(cr0 + ca), __ldg(cr0 + ca + 32));
        cp1[p] = pk(__ldg(cr1 + ca), __ldg(cr1 + ca + 32));
    }

    // ---- Phase 2: mixing MLP (abs half only; linear half analytic) ----
    u64 A2 = ABs[0], B2 = ABs[1];
    u64 s0[4], s1[4];
    #pragma unroll
    for (int p = 0; p < 4; p++) {
        s0[p] = fma2_(B2, cp0[p], mul2_(A2, dp0[p]));
        s1[p] = fma2_(B2, cp1[p], mul2_(A2, dp1[p]));
    }
    #pragma unroll 4
    for (int m = 0; m < 32; m++) {
        ulonglong2 w01 = *(const ulonglong2*)&mlpp[m][0];
        ulonglong2 w23 = *(const ulonglong2*)&mlpp[m][2];
        u64 wxx = w01.x, wyy = w01.y, wzz = w23.x, hww = w23.y;
        #pragma unroll
        for (int p = 0; p < 4; p++) {
            u64 t0 = fma2_(wxx, dp0[p], fma2_(wyy, cp0[p], wzz));
            s0[p] = fma2_(hww, t0 & ABSM, s0[p]);
            u64 t1 = fma2_(wxx, dp1[p], fma2_(wyy, cp1[p], wzz));
            s1[p] = fma2_(hww, t1 & ABSM, s1[p]);
        }
    }

    // ---- Phase 3: softmax per row ----
    float sc0[8], sc1[8];
    #pragma unroll
    for (int p = 0; p < 4; p++) {
        upk(s0[p], sc0[2 * p], sc0[2 * p + 1]);
        upk(s1[p], sc1[2 * p], sc1[2 * p + 1]);
    }
    float mx0 = sc0[0], mx1 = sc1[0];
    #pragma unroll
    for (int i = 1; i < 8; i++) { mx0 = fmaxf(mx0, sc0[i]); mx1 = fmaxf(mx1, sc1[i]); }
    #pragma unroll
    for (int o = 16; o; o >>= 1) {
        mx0 = fmaxf(mx0, __shfl_xor_sync(0xffffffffu, mx0, o));
        mx1 = fmaxf(mx1, __shfl_xor_sync(0xffffffffu, mx1, o));
    }
    float sum0 = 0.f, sum1 = 0.f;
    #pragma unroll
    for (int i = 0; i < 8; i++) {
        sc0[i] = __expf(sc0[i] - mx0); sum0 += sc0[i];
        sc1[i] = __expf(sc1[i] - mx1); sum1 += sc1[i];
    }
    #pragma unroll
    for (int o = 16; o; o >>= 1) {
        sum0 += __shfl_xor_sync(0xffffffffu, sum0, o);
        sum1 += __shfl_xor_sync(0xffffffffu, sum1, o);
    }
    float inv0 = 1.f / sum0, inv1 = 1.f / sum1;

    // ---- Phase 4: AV accumulation (packed over d pairs) ----
    u64 acc0[8], acc1[8];
    #pragma unroll
    for (int j = 0; j < 8; j++) { acc0[j] = 0ull; acc1[j] = 0ull; }
    #pragma unroll
    for (int i = 0; i < 8; i++) {
        int c = i * 32 + lane;
        u64 w0 = pk(sc0[i], sc0[i]);
        u64 w1 = pk(sc1[i], sc1[i]);
        #pragma unroll
        for (int j = 0; j < 4; j++) {
            float4 vv = *(const float4*)&Vs[c][j * 4];
            u64 vA = pk(vv.x, vv.y);
            u64 vB = pk(vv.z, vv.w);
            acc0[2 * j]     = fma2_(w0, vA, acc0[2 * j]);
            acc0[2 * j + 1] = fma2_(w0, vB, acc0[2 * j + 1]);
            acc1[2 * j]     = fma2_(w1, vA, acc1[2 * j]);
            acc1[2 * j + 1] = fma2_(w1, vB, acc1[2 * j + 1]);
        }
    }

    // ---- Phase 5: reduce-scatter epilogue ----
    int d0;
    float res0 = reduce16(acc0, lane, d0);
    int d1;
    float res1 = reduce16(acc1, lane, d1);
    if ((lane & 1) == 0) {
        out[(b * NQ + r0)     * (H_ * D_) + h * D_ + d0] = res0 * inv0;
        out[(b * NQ + r0 + 1) * (H_ * D_) + h * D_ + d1] = res1 * inv1;
    }
}

extern "C" void kernel_launch(void* const* d_in, const int* in_sizes, int n_in,
                              void* d_out, int out_size)
{
    const float* row_emb  = (const float*)d_in[0];
    const float* col_emb  = (const float*)d_in[1];
    const float* cost_mat = (const float*)d_in[2];
    const float* Wq       = (const float*)d_in[3];
    const float* Wk       = (const float*)d_in[4];
    const float* Wv       = (const float*)d_in[5];
    const float* m1w      = (const float*)d_in[6];
    const float* m1b      = (const float*)d_in[7];
    const float* m2w      = (const float*)d_in[8];
    // d_in[9] = mix2_bias: softmax-invariant, intentionally unused.
    float* out = (float*)d_out;

    dim3 gA(4, 16, 3);   // n-tiles x m-tiles x {Q,K,V}
    qkv_kernel<<<gA, 256>>>(row_emb, col_emb, Wq, Wk, Wv);

    dim3 gB(16, 16, 4);  // 16-row tiles x heads x batch
    attn_kernel<<<gB, 256>>>(cost_mat, m1w, m1b, m2w, out);
}